// round 1
// baseline (speedup 1.0000x reference)
#include <cuda_runtime.h>
#include <math.h>

// Problem constants (fixed by the reference)
#define B_WIN   2048
#define N_TOK   64
#define DIM     512
#define HEADS   16
#define DH      32
#define QKV_DIM 1536
#define WIN     8
#define REL_SZ  15     // 2*WIN-1
#define M_ROWS  (B_WIN * N_TOK)   // 131072

// Scratch (no cudaMalloc allowed)
__device__ float g_qkv[(size_t)M_ROWS * QKV_DIM];   // [M, 1536] = [b*64+n, s*512 + h*32 + d]
__device__ float g_att[(size_t)M_ROWS * DIM];       // [M, 512]

// ---------------------------------------------------------------------------
// SGEMM: C[M,N] = A[M,K] @ B[K,N] + bias[N]
// BM=128, BN=128, BK=8, TM=TN=8, 256 threads.
// Requires M%128==0, N%128==0, K%8==0 (true for all our shapes).
// ---------------------------------------------------------------------------
#define BM 128
#define BN 128
#define BK 8
#define TM 8
#define TN 8

__global__ __launch_bounds__(256, 2)
void sgemm_bias(const float* __restrict__ A, const float* __restrict__ Bm,
                const float* __restrict__ bias, float* __restrict__ C,
                int M, int N, int K)
{
    const int cRow = blockIdx.y;
    const int cCol = blockIdx.x;
    const int tid  = threadIdx.x;

    const int threadCol = tid % (BN / TN);   // 0..15
    const int threadRow = tid / (BN / TN);   // 0..15

    __shared__ float As[BK][BM];
    __shared__ float Bs[BK][BN];

    const float* Ablk = A + (size_t)cRow * BM * K;
    const float* Bblk = Bm + cCol * BN;

    // A tile loaders: 128 rows x 8 cols, one float4 per thread
    const int innerRowA = tid >> 1;          // 0..127
    const int innerColA = (tid & 1) * 4;     // 0 or 4
    // B tile loaders: 8 rows x 128 cols, one float4 per thread
    const int innerRowB = tid >> 5;          // 0..7
    const int innerColB = (tid & 31) * 4;    // 0..124

    float acc[TM][TN];
    #pragma unroll
    for (int m = 0; m < TM; m++)
        #pragma unroll
        for (int n = 0; n < TN; n++)
            acc[m][n] = 0.0f;

    float regM[TM], regN[TN];

    for (int k0 = 0; k0 < K; k0 += BK) {
        float4 a = *reinterpret_cast<const float4*>(Ablk + (size_t)innerRowA * K + k0 + innerColA);
        As[innerColA + 0][innerRowA] = a.x;
        As[innerColA + 1][innerRowA] = a.y;
        As[innerColA + 2][innerRowA] = a.z;
        As[innerColA + 3][innerRowA] = a.w;

        *reinterpret_cast<float4*>(&Bs[innerRowB][innerColB]) =
            *reinterpret_cast<const float4*>(Bblk + (size_t)(k0 + innerRowB) * N + innerColB);

        __syncthreads();

        #pragma unroll
        for (int k = 0; k < BK; k++) {
            #pragma unroll
            for (int m = 0; m < TM; m++) regM[m] = As[k][threadRow * TM + m];
            #pragma unroll
            for (int n = 0; n < TN; n++) regN[n] = Bs[k][threadCol * TN + n];
            #pragma unroll
            for (int m = 0; m < TM; m++)
                #pragma unroll
                for (int n = 0; n < TN; n++)
                    acc[m][n] = fmaf(regM[m], regN[n], acc[m][n]);
        }
        __syncthreads();
    }

    // Epilogue: add bias, vectorized store
    #pragma unroll
    for (int m = 0; m < TM; m++) {
        const size_t row = (size_t)cRow * BM + threadRow * TM + m;
        #pragma unroll
        for (int n = 0; n < TN; n += 4) {
            const int col = cCol * BN + threadCol * TN + n;
            float4 bv = *reinterpret_cast<const float4*>(bias + col);
            float4 o;
            o.x = acc[m][n + 0] + bv.x;
            o.y = acc[m][n + 1] + bv.y;
            o.z = acc[m][n + 2] + bv.z;
            o.w = acc[m][n + 3] + bv.w;
            *reinterpret_cast<float4*>(C + row * N + col) = o;
        }
    }
}

// ---------------------------------------------------------------------------
// Attention: one block per (window b, head h), 64 threads (thread i = query i)
// q in registers (pre-scaled), k/v/scores in shared.
// ---------------------------------------------------------------------------
__global__ __launch_bounds__(64)
void attn_kernel(const float* __restrict__ rel)
{
    const int b = blockIdx.x;
    const int h = blockIdx.y;
    const int i = threadIdx.x;

    __shared__ float ks[N_TOK][DH + 1];
    __shared__ float vs[N_TOK][DH + 1];
    __shared__ float sc[N_TOK][N_TOK + 1];

    const size_t base = ((size_t)(b * N_TOK + i)) * QKV_DIM + h * DH;

    // load K row i and V row i into shared
    #pragma unroll
    for (int d = 0; d < DH; d += 4) {
        float4 kk = *reinterpret_cast<const float4*>(&g_qkv[base + 512 + d]);
        ks[i][d + 0] = kk.x; ks[i][d + 1] = kk.y; ks[i][d + 2] = kk.z; ks[i][d + 3] = kk.w;
        float4 vv = *reinterpret_cast<const float4*>(&g_qkv[base + 1024 + d]);
        vs[i][d + 0] = vv.x; vs[i][d + 1] = vv.y; vs[i][d + 2] = vv.z; vs[i][d + 3] = vv.w;
    }

    const float scale = 0.17677669529663687f;  // 32^-0.5
    float q[DH];
    #pragma unroll
    for (int d = 0; d < DH; d += 4) {
        float4 qq = *reinterpret_cast<const float4*>(&g_qkv[base + d]);
        q[d + 0] = qq.x * scale; q[d + 1] = qq.y * scale;
        q[d + 2] = qq.z * scale; q[d + 3] = qq.w * scale;
    }
    __syncthreads();

    const int yi = i >> 3, xi = i & 7;
    const float* relh = rel + h * REL_SZ * REL_SZ;

    float mx = -1e30f;
    for (int j = 0; j < N_TOK; j++) {
        float s = 0.0f;
        #pragma unroll
        for (int d = 0; d < DH; d++) s = fmaf(q[d], ks[j][d], s);
        const int yj = j >> 3, xj = j & 7;
        s += relh[(yi - yj + 7) * REL_SZ + (xi - xj + 7)];
        sc[i][j] = s;
        mx = fmaxf(mx, s);
    }

    float sum = 0.0f;
    for (int j = 0; j < N_TOK; j++) {
        float e = __expf(sc[i][j] - mx);
        sc[i][j] = e;
        sum += e;
    }
    const float inv = 1.0f / sum;

    float out[DH];
    #pragma unroll
    for (int d = 0; d < DH; d++) out[d] = 0.0f;

    for (int j = 0; j < N_TOK; j++) {
        const float p = sc[i][j];
        #pragma unroll
        for (int d = 0; d < DH; d++) out[d] = fmaf(p, vs[j][d], out[d]);
    }

    const size_t obase = ((size_t)(b * N_TOK + i)) * DIM + h * DH;
    #pragma unroll
    for (int d = 0; d < DH; d += 4) {
        float4 o;
        o.x = out[d + 0] * inv; o.y = out[d + 1] * inv;
        o.z = out[d + 2] * inv; o.w = out[d + 3] * inv;
        *reinterpret_cast<float4*>(&g_att[obase + d]) = o;
    }
}

// ---------------------------------------------------------------------------
// Launch
// ---------------------------------------------------------------------------
extern "C" void kernel_launch(void* const* d_in, const int* in_sizes, int n_in,
                              void* d_out, int out_size)
{
    const float* x      = (const float*)d_in[0];  // [2048,64,512]
    const float* w_qkv  = (const float*)d_in[1];  // [512,1536]
    const float* b_qkv  = (const float*)d_in[2];  // [1536]
    const float* rel    = (const float*)d_in[3];  // [16,15,15]
    const float* w_proj = (const float*)d_in[4];  // [512,512]
    const float* b_proj = (const float*)d_in[5];  // [512]
    float* out = (float*)d_out;                   // [2048,64,512]
    (void)in_sizes; (void)n_in; (void)out_size;

    float* qkv = nullptr;
    float* att = nullptr;
    cudaGetSymbolAddress((void**)&qkv, g_qkv);
    cudaGetSymbolAddress((void**)&att, g_att);

    // 1) QKV GEMM: [131072,512] @ [512,1536] + b_qkv
    {
        dim3 grid(QKV_DIM / BN, M_ROWS / BM);   // (12, 1024)
        sgemm_bias<<<grid, 256>>>(x, w_qkv, b_qkv, qkv, M_ROWS, QKV_DIM, DIM);
    }

    // 2) Windowed attention with relative position bias
    {
        dim3 grid(B_WIN, HEADS);                 // (2048, 16)
        attn_kernel<<<grid, 64>>>(rel);
    }

    // 3) Output projection: [131072,512] @ [512,512] + b_proj
    {
        dim3 grid(DIM / BN, M_ROWS / BM);        // (4, 1024)
        sgemm_bias<<<grid, 256>>>(att, w_proj, b_proj, out, M_ROWS, DIM, DIM);
    }
}

// round 2
// speedup vs baseline: 2.9256x; 2.9256x over previous
#include <cuda_runtime.h>
#include <math.h>
#include <stdint.h>

// Problem constants
#define B_WIN   2048
#define N_TOK   64
#define DIM     512
#define HEADS   16
#define DH      32
#define QKV_DIM 1536
#define WIN     8
#define REL_SZ  15
#define M_ROWS  (B_WIN * N_TOK)   // 131072

// Scratch (no cudaMalloc allowed)
__device__ float g_qkv[(size_t)M_ROWS * QKV_DIM];
__device__ float g_att[(size_t)M_ROWS * DIM];

// ---------------------------------------------------------------------------
// TF32 tensor-core GEMM: C[M,N] = A[M,K] @ B[K,N] + bias[N]
// BM=128, BN=128, BK=16. 256 threads = 8 warps (2 x 4). Warp tile 64x32.
// mma.sync.aligned.m16n8k8.row.col.f32.tf32.tf32.f32, fp32 accumulate.
// cp.async double-buffered. Requires M%128==0, N%128==0, K%16==0.
// ---------------------------------------------------------------------------
#define GBM 128
#define GBN 128
#define GBK 16
#define APAD 4    // As[m][GBK+4]: conflict-free frag loads
#define BPAD 8    // Bs[k][GBN+8]: conflict-free frag loads

__device__ __forceinline__ uint32_t f2tf32(float x) {
    uint32_t u;
    asm("cvt.rna.tf32.f32 %0, %1;" : "=r"(u) : "f"(x));
    return u;
}

__device__ __forceinline__ void cp_async16(void* smem_dst, const void* gmem_src) {
    uint32_t s = (uint32_t)__cvta_generic_to_shared(smem_dst);
    asm volatile("cp.async.cg.shared.global [%0], [%1], 16;\n" :: "r"(s), "l"(gmem_src));
}

__global__ __launch_bounds__(256, 2)
void gemm_tf32(const float* __restrict__ A, const float* __restrict__ B,
               const float* __restrict__ bias, float* __restrict__ C,
               int M, int N, int K)
{
    __shared__ float As[2][GBM][GBK + APAD];   // 2*128*20*4 = 20480 B
    __shared__ float Bs[2][GBK][GBN + BPAD];   // 2*16*136*4 = 17408 B

    const int tid  = threadIdx.x;
    const int warp = tid >> 5;
    const int lane = tid & 31;
    const int wm = warp & 1;          // 0..1  (64 rows each)
    const int wn = warp >> 1;         // 0..3  (32 cols each)
    const int g  = lane >> 2;         // 0..7
    const int t  = lane & 3;          // 0..3

    const int cm = blockIdx.y * GBM;
    const int cn = blockIdx.x * GBN;

    // global->smem load indices
    const int arow = tid >> 2;        // 0..63  (rows arow, arow+64)
    const int acol = (tid & 3) * 4;   // 0,4,8,12
    const int brow = tid >> 5;        // 0..7   (rows brow, brow+8)
    const int bcol = (tid & 31) * 4;  // 0..124

    const float* Abase = A + (size_t)(cm + arow) * K + acol;
    const float* Bbase = B + (size_t)brow * N + cn + bcol;

    float acc[4][4][4];
    #pragma unroll
    for (int i = 0; i < 4; i++)
        #pragma unroll
        for (int j = 0; j < 4; j++)
            #pragma unroll
            for (int r = 0; r < 4; r++)
                acc[i][j][r] = 0.0f;

    const int KT = K / GBK;

    // prologue: stage 0
    {
        cp_async16(&As[0][arow][acol],      Abase);
        cp_async16(&As[0][arow + 64][acol], Abase + (size_t)64 * K);
        cp_async16(&Bs[0][brow][bcol],      Bbase);
        cp_async16(&Bs[0][brow + 8][bcol],  Bbase + (size_t)8 * N);
        asm volatile("cp.async.commit_group;\n");
    }

    for (int kt = 0; kt < KT; kt++) {
        const int st = kt & 1;
        if (kt + 1 < KT) {
            const int ns = (kt + 1) & 1;
            const int k0 = (kt + 1) * GBK;
            cp_async16(&As[ns][arow][acol],      Abase + k0);
            cp_async16(&As[ns][arow + 64][acol], Abase + (size_t)64 * K + k0);
            cp_async16(&Bs[ns][brow][bcol],      Bbase + (size_t)k0 * N);
            cp_async16(&Bs[ns][brow + 8][bcol],  Bbase + (size_t)(k0 + 8) * N);
            asm volatile("cp.async.commit_group;\n");
            asm volatile("cp.async.wait_group 1;\n");
        } else {
            asm volatile("cp.async.wait_group 0;\n");
        }
        __syncthreads();

        #pragma unroll
        for (int kk = 0; kk < 2; kk++) {
            const int k8 = kk * 8;
            uint32_t af[4][4];
            #pragma unroll
            for (int mt = 0; mt < 4; mt++) {
                const int m0 = wm * 64 + mt * 16;
                af[mt][0] = f2tf32(As[st][m0 + g    ][k8 + t    ]);
                af[mt][1] = f2tf32(As[st][m0 + g + 8][k8 + t    ]);
                af[mt][2] = f2tf32(As[st][m0 + g    ][k8 + t + 4]);
                af[mt][3] = f2tf32(As[st][m0 + g + 8][k8 + t + 4]);
            }
            uint32_t bf[4][2];
            #pragma unroll
            for (int nt = 0; nt < 4; nt++) {
                const int n0 = wn * 32 + nt * 8;
                bf[nt][0] = f2tf32(Bs[st][k8 + t    ][n0 + g]);
                bf[nt][1] = f2tf32(Bs[st][k8 + t + 4][n0 + g]);
            }
            #pragma unroll
            for (int mt = 0; mt < 4; mt++)
                #pragma unroll
                for (int nt = 0; nt < 4; nt++) {
                    asm volatile(
                        "mma.sync.aligned.m16n8k8.row.col.f32.tf32.tf32.f32 "
                        "{%0,%1,%2,%3}, {%4,%5,%6,%7}, {%8,%9}, {%0,%1,%2,%3};\n"
                        : "+f"(acc[mt][nt][0]), "+f"(acc[mt][nt][1]),
                          "+f"(acc[mt][nt][2]), "+f"(acc[mt][nt][3])
                        : "r"(af[mt][0]), "r"(af[mt][1]), "r"(af[mt][2]), "r"(af[mt][3]),
                          "r"(bf[nt][0]), "r"(bf[nt][1]));
                }
        }
        __syncthreads();
    }

    // epilogue: add bias, store
    #pragma unroll
    for (int mt = 0; mt < 4; mt++) {
        const size_t r0 = (size_t)cm + wm * 64 + mt * 16 + g;
        #pragma unroll
        for (int nt = 0; nt < 4; nt++) {
            const int col = cn + wn * 32 + nt * 8 + 2 * t;
            const float2 bv = *reinterpret_cast<const float2*>(bias + col);
            float2 o0, o1;
            o0.x = acc[mt][nt][0] + bv.x;
            o0.y = acc[mt][nt][1] + bv.y;
            o1.x = acc[mt][nt][2] + bv.x;
            o1.y = acc[mt][nt][3] + bv.y;
            *reinterpret_cast<float2*>(C + r0 * N + col)       = o0;
            *reinterpret_cast<float2*>(C + (r0 + 8) * N + col) = o1;
        }
    }
}

// ---------------------------------------------------------------------------
// Attention: one block per (window b, head h), 64 threads. Scores in regs,
// rel-pos bias table in smem, k/v in smem.
// ---------------------------------------------------------------------------
__global__ __launch_bounds__(64)
void attn_kernel(const float* __restrict__ rel)
{
    const int b = blockIdx.x;
    const int h = blockIdx.y;
    const int i = threadIdx.x;

    __shared__ float ks[N_TOK][DH + 1];
    __shared__ float vs[N_TOK][DH + 1];
    __shared__ float rels[REL_SZ * REL_SZ];

    const size_t base = ((size_t)(b * N_TOK + i)) * QKV_DIM + h * DH;

    #pragma unroll
    for (int d = 0; d < DH; d += 4) {
        float4 kk = *reinterpret_cast<const float4*>(&g_qkv[base + 512 + d]);
        ks[i][d + 0] = kk.x; ks[i][d + 1] = kk.y; ks[i][d + 2] = kk.z; ks[i][d + 3] = kk.w;
        float4 vv = *reinterpret_cast<const float4*>(&g_qkv[base + 1024 + d]);
        vs[i][d + 0] = vv.x; vs[i][d + 1] = vv.y; vs[i][d + 2] = vv.z; vs[i][d + 3] = vv.w;
    }
    const float* relh = rel + h * REL_SZ * REL_SZ;
    #pragma unroll
    for (int p = i; p < REL_SZ * REL_SZ; p += 64) rels[p] = relh[p];

    const float scale = 0.17677669529663687f;  // 32^-0.5
    float q[DH];
    #pragma unroll
    for (int d = 0; d < DH; d += 4) {
        float4 qq = *reinterpret_cast<const float4*>(&g_qkv[base + d]);
        q[d + 0] = qq.x * scale; q[d + 1] = qq.y * scale;
        q[d + 2] = qq.z * scale; q[d + 3] = qq.w * scale;
    }
    __syncthreads();

    const int yi = i >> 3, xi = i & 7;

    float sc[N_TOK];
    float mx = -1e30f;
    #pragma unroll
    for (int j = 0; j < N_TOK; j++) {
        float s = 0.0f;
        #pragma unroll
        for (int d = 0; d < DH; d++) s = fmaf(q[d], ks[j][d], s);
        const int yj = j >> 3, xj = j & 7;
        s += rels[(yi - yj + 7) * REL_SZ + (xi - xj + 7)];
        sc[j] = s;
        mx = fmaxf(mx, s);
    }

    float sum = 0.0f;
    #pragma unroll
    for (int j = 0; j < N_TOK; j++) {
        const float e = __expf(sc[j] - mx);
        sc[j] = e;
        sum += e;
    }
    const float inv = 1.0f / sum;

    float out[DH];
    #pragma unroll
    for (int d = 0; d < DH; d++) out[d] = 0.0f;
    #pragma unroll
    for (int j = 0; j < N_TOK; j++) {
        const float p = sc[j];
        #pragma unroll
        for (int d = 0; d < DH; d++) out[d] = fmaf(p, vs[j][d], out[d]);
    }

    const size_t obase = ((size_t)(b * N_TOK + i)) * DIM + h * DH;
    #pragma unroll
    for (int d = 0; d < DH; d += 4) {
        float4 o;
        o.x = out[d + 0] * inv; o.y = out[d + 1] * inv;
        o.z = out[d + 2] * inv; o.w = out[d + 3] * inv;
        *reinterpret_cast<float4*>(&g_att[obase + d]) = o;
    }
}

// ---------------------------------------------------------------------------
// Launch
// ---------------------------------------------------------------------------
extern "C" void kernel_launch(void* const* d_in, const int* in_sizes, int n_in,
                              void* d_out, int out_size)
{
    const float* x      = (const float*)d_in[0];
    const float* w_qkv  = (const float*)d_in[1];
    const float* b_qkv  = (const float*)d_in[2];
    const float* rel    = (const float*)d_in[3];
    const float* w_proj = (const float*)d_in[4];
    const float* b_proj = (const float*)d_in[5];
    float* out = (float*)d_out;
    (void)in_sizes; (void)n_in; (void)out_size;

    float* qkv = nullptr;
    float* att = nullptr;
    cudaGetSymbolAddress((void**)&qkv, g_qkv);
    cudaGetSymbolAddress((void**)&att, g_att);

    // 1) QKV GEMM: [131072,512] @ [512,1536] + b_qkv
    {
        dim3 grid(QKV_DIM / GBN, M_ROWS / GBM);   // (12, 1024)
        gemm_tf32<<<grid, 256>>>(x, w_qkv, b_qkv, qkv, M_ROWS, QKV_DIM, DIM);
    }

    // 2) Windowed attention
    {
        dim3 grid(B_WIN, HEADS);
        attn_kernel<<<grid, 64>>>(rel);
    }

    // 3) Output projection: [131072,512] @ [512,512] + b_proj
    {
        dim3 grid(DIM / GBN, M_ROWS / GBM);       // (4, 1024)
        gemm_tf32<<<grid, 256>>>(att, w_proj, b_proj, out, M_ROWS, DIM, DIM);
    }
}

// round 4
// speedup vs baseline: 2.9855x; 1.0205x over previous
#include <cuda_runtime.h>
#include <math.h>
#include <stdint.h>

// Problem constants
#define B_WIN   2048
#define N_TOK   64
#define DIM     512
#define HEADS   16
#define DH      32
#define QKV_DIM 1536
#define WIN     8
#define REL_SZ  15
#define M_ROWS  (B_WIN * N_TOK)   // 131072

// Scratch (no cudaMalloc allowed)
__device__ float g_qkv[(size_t)M_ROWS * QKV_DIM];      // fp32 qkv for attention
__device__ float g_att[(size_t)M_ROWS * DIM];          // attention out (tf32-rounded)
__device__ float g_xc[(size_t)M_ROWS * DIM];           // x, tf32-rounded
__device__ float g_wqkv_c[(size_t)DIM * QKV_DIM];      // w_qkv, tf32-rounded
__device__ float g_wproj_c[(size_t)DIM * DIM];         // w_proj, tf32-rounded

__device__ __forceinline__ uint32_t f2tf32(float x) {
    uint32_t u;
    asm("cvt.rna.tf32.f32 %0, %1;" : "=r"(u) : "f"(x));
    return u;
}

// ---------------------------------------------------------------------------
// Elementwise TF32 pre-round (stores rounded value as float; low 13 bits zero)
// ---------------------------------------------------------------------------
__global__ void cvt_tf32_pass(const float4* __restrict__ in, float4* __restrict__ out, int n4)
{
    for (int i = blockIdx.x * blockDim.x + threadIdx.x; i < n4; i += gridDim.x * blockDim.x) {
        float4 v = in[i];
        float4 o;
        o.x = __uint_as_float(f2tf32(v.x));
        o.y = __uint_as_float(f2tf32(v.y));
        o.z = __uint_as_float(f2tf32(v.z));
        o.w = __uint_as_float(f2tf32(v.w));
        out[i] = o;
    }
}

// ---------------------------------------------------------------------------
// TF32 tensor-core GEMM: C[M,N] = A[M,K] @ B[K,N] + bias[N]
// Inputs MUST already be tf32-rounded. BM=128, BN=128, BK=16, 8 warps,
// warp tile 64x32, 3-stage cp.async pipeline, dynamic smem.
// ---------------------------------------------------------------------------
#define GBM 128
#define GBN 128
#define GBK 16
#define APAD 4
#define BPAD 8
#define AS_STRIDE (GBK + APAD)          // 20
#define BS_STRIDE (GBN + BPAD)          // 136
#define AS_STAGE (GBM * AS_STRIDE)      // 2560 floats
#define BS_STAGE (GBK * BS_STRIDE)      // 2176 floats
#define SMEM_BYTES ((AS_STAGE + BS_STAGE) * 3 * 4)   // 56832

__device__ __forceinline__ void cp_async16(void* smem_dst, const void* gmem_src) {
    uint32_t s = (uint32_t)__cvta_generic_to_shared(smem_dst);
    asm volatile("cp.async.cg.shared.global [%0], [%1], 16;\n" :: "r"(s), "l"(gmem_src));
}

__global__ __launch_bounds__(256, 2)
void gemm_tf32(const float* __restrict__ A, const float* __restrict__ B,
               const float* __restrict__ bias, float* __restrict__ C,
               int M, int N, int K)
{
    extern __shared__ float sm[];
    float* As = sm;                     // [3][128][20]
    float* Bs = sm + 3 * AS_STAGE;      // [3][16][136]

    const int tid  = threadIdx.x;
    const int warp = tid >> 5;
    const int lane = tid & 31;
    const int wm = warp & 1;
    const int wn = warp >> 1;
    const int g  = lane >> 2;
    const int t  = lane & 3;

    const int cm = blockIdx.y * GBM;
    const int cn = blockIdx.x * GBN;

    const int arow = tid >> 2;
    const int acol = (tid & 3) * 4;
    const int brow = tid >> 5;
    const int bcol = (tid & 31) * 4;

    const float* Abase = A + (size_t)(cm + arow) * K + acol;
    const float* Bbase = B + (size_t)brow * N + cn + bcol;

    float acc[4][4][4];
    #pragma unroll
    for (int i = 0; i < 4; i++)
        #pragma unroll
        for (int j = 0; j < 4; j++)
            #pragma unroll
            for (int r = 0; r < 4; r++)
                acc[i][j][r] = 0.0f;

    const int KT = K / GBK;

    auto issue_stage = [&](int kt, int st) {
        const int k0 = kt * GBK;
        float* as = As + st * AS_STAGE;
        float* bs = Bs + st * BS_STAGE;
        cp_async16(&as[arow * AS_STRIDE + acol],        Abase + k0);
        cp_async16(&as[(arow + 64) * AS_STRIDE + acol], Abase + (size_t)64 * K + k0);
        cp_async16(&bs[brow * BS_STRIDE + bcol],        Bbase + (size_t)k0 * N);
        cp_async16(&bs[(brow + 8) * BS_STRIDE + bcol],  Bbase + (size_t)(k0 + 8) * N);
        asm volatile("cp.async.commit_group;\n");
    };

    issue_stage(0, 0);
    issue_stage(1, 1);

    for (int kt = 0; kt < KT; kt++) {
        const int st = kt % 3;
        if (kt == KT - 1) {
            asm volatile("cp.async.wait_group 0;\n");
        } else {
            asm volatile("cp.async.wait_group 1;\n");
        }
        __syncthreads();

        if (kt + 2 < KT) issue_stage(kt + 2, (kt + 2) % 3);

        const float* as = As + st * AS_STAGE;
        const float* bs = Bs + st * BS_STAGE;

        #pragma unroll
        for (int kk = 0; kk < 2; kk++) {
            const int k8 = kk * 8;
            uint32_t af[4][4];
            #pragma unroll
            for (int mt = 0; mt < 4; mt++) {
                const int m0 = wm * 64 + mt * 16;
                af[mt][0] = __float_as_uint(as[(m0 + g    ) * AS_STRIDE + k8 + t    ]);
                af[mt][1] = __float_as_uint(as[(m0 + g + 8) * AS_STRIDE + k8 + t    ]);
                af[mt][2] = __float_as_uint(as[(m0 + g    ) * AS_STRIDE + k8 + t + 4]);
                af[mt][3] = __float_as_uint(as[(m0 + g + 8) * AS_STRIDE + k8 + t + 4]);
            }
            uint32_t bf[4][2];
            #pragma unroll
            for (int nt = 0; nt < 4; nt++) {
                const int n0 = wn * 32 + nt * 8;
                bf[nt][0] = __float_as_uint(bs[(k8 + t    ) * BS_STRIDE + n0 + g]);
                bf[nt][1] = __float_as_uint(bs[(k8 + t + 4) * BS_STRIDE + n0 + g]);
            }
            #pragma unroll
            for (int mt = 0; mt < 4; mt++)
                #pragma unroll
                for (int nt = 0; nt < 4; nt++) {
                    asm volatile(
                        "mma.sync.aligned.m16n8k8.row.col.f32.tf32.tf32.f32 "
                        "{%0,%1,%2,%3}, {%4,%5,%6,%7}, {%8,%9}, {%0,%1,%2,%3};\n"
                        : "+f"(acc[mt][nt][0]), "+f"(acc[mt][nt][1]),
                          "+f"(acc[mt][nt][2]), "+f"(acc[mt][nt][3])
                        : "r"(af[mt][0]), "r"(af[mt][1]), "r"(af[mt][2]), "r"(af[mt][3]),
                          "r"(bf[nt][0]), "r"(bf[nt][1]));
                }
        }
        __syncthreads();
    }

    #pragma unroll
    for (int mt = 0; mt < 4; mt++) {
        const size_t r0 = (size_t)cm + wm * 64 + mt * 16 + g;
        #pragma unroll
        for (int nt = 0; nt < 4; nt++) {
            const int col = cn + wn * 32 + nt * 8 + 2 * t;
            const float2 bv = *reinterpret_cast<const float2*>(bias + col);
            float2 o0, o1;
            o0.x = acc[mt][nt][0] + bv.x;
            o0.y = acc[mt][nt][1] + bv.y;
            o1.x = acc[mt][nt][2] + bv.x;
            o1.y = acc[mt][nt][3] + bv.y;
            *reinterpret_cast<float2*>(C + r0 * N + col)       = o0;
            *reinterpret_cast<float2*>(C + (r0 + 8) * N + col) = o1;
        }
    }
}

// ---------------------------------------------------------------------------
// Attention: one block per (window b, head h), 64 threads.
// Coalesced smem staging, float4 broadcast LDS, scores in registers.
// Output written TF32-rounded (so the proj GEMM needs no cvt).
// ---------------------------------------------------------------------------
#define PADW 36   // row stride in floats: keeps float4 alignment for all rows

__global__ __launch_bounds__(64)
void attn_kernel(const float* __restrict__ rel)
{
    const int b = blockIdx.x;
    const int h = blockIdx.y;
    const int tid = threadIdx.x;

    __shared__ float qs[N_TOK][PADW];
    __shared__ float ks[N_TOK][PADW];
    __shared__ float vs[N_TOK][PADW];
    __shared__ float rels[REL_SZ * REL_SZ];

    const float* gq = g_qkv + (size_t)b * N_TOK * QKV_DIM + h * DH;

    // coalesced fill: 512 float4 per matrix; 8 consecutive threads cover one row
    for (int idx = tid; idx < N_TOK * 8; idx += 64) {
        const int m = idx >> 3;
        const int c = (idx & 7) * 4;
        const float* p = gq + (size_t)m * QKV_DIM + c;
        *reinterpret_cast<float4*>(&qs[m][c]) = *reinterpret_cast<const float4*>(p);
        *reinterpret_cast<float4*>(&ks[m][c]) = *reinterpret_cast<const float4*>(p + 512);
        *reinterpret_cast<float4*>(&vs[m][c]) = *reinterpret_cast<const float4*>(p + 1024);
    }
    for (int p = tid; p < REL_SZ * REL_SZ; p += 64) rels[p] = rel[h * REL_SZ * REL_SZ + p];
    __syncthreads();

    const int i = tid;
    const float scale = 0.17677669529663687f;
    float q[DH];
    #pragma unroll
    for (int d = 0; d < DH; d++) q[d] = qs[i][d] * scale;

    const int yi = i >> 3, xi = i & 7;

    float sc[N_TOK];
    float mx = -1e30f;
    #pragma unroll
    for (int j = 0; j < N_TOK; j++) {
        float s0 = 0.f, s1 = 0.f, s2 = 0.f, s3 = 0.f;
        #pragma unroll
        for (int d = 0; d < DH; d += 4) {
            const float4 kk = *reinterpret_cast<const float4*>(&ks[j][d]);
            s0 = fmaf(q[d + 0], kk.x, s0);
            s1 = fmaf(q[d + 1], kk.y, s1);
            s2 = fmaf(q[d + 2], kk.z, s2);
            s3 = fmaf(q[d + 3], kk.w, s3);
        }
        const int yj = j >> 3, xj = j & 7;
        const float s = (s0 + s1) + (s2 + s3) + rels[(yi - yj + 7) * REL_SZ + (xi - xj + 7)];
        sc[j] = s;
        mx = fmaxf(mx, s);
    }

    float sum = 0.0f;
    #pragma unroll
    for (int j = 0; j < N_TOK; j++) {
        const float e = __expf(sc[j] - mx);
        sc[j] = e;
        sum += e;
    }
    const float inv = 1.0f / sum;

    float out[DH];
    #pragma unroll
    for (int d = 0; d < DH; d++) out[d] = 0.0f;
    #pragma unroll
    for (int j = 0; j < N_TOK; j++) {
        const float p = sc[j];
        #pragma unroll
        for (int d = 0; d < DH; d += 4) {
            const float4 vv = *reinterpret_cast<const float4*>(&vs[j][d]);
            out[d + 0] = fmaf(p, vv.x, out[d + 0]);
            out[d + 1] = fmaf(p, vv.y, out[d + 1]);
            out[d + 2] = fmaf(p, vv.z, out[d + 2]);
            out[d + 3] = fmaf(p, vv.w, out[d + 3]);
        }
    }

    // stage output (tf32-rounded) back through qs for coalesced store
    #pragma unroll
    for (int d = 0; d < DH; d++)
        qs[i][d] = __uint_as_float(f2tf32(out[d] * inv));
    __syncthreads();

    float* go = g_att + (size_t)b * N_TOK * DIM + h * DH;
    for (int idx = tid; idx < N_TOK * 8; idx += 64) {
        const int m = idx >> 3;
        const int c = (idx & 7) * 4;
        *reinterpret_cast<float4*>(go + (size_t)m * DIM + c) =
            *reinterpret_cast<const float4*>(&qs[m][c]);
    }
}

// ---------------------------------------------------------------------------
// Launch
// ---------------------------------------------------------------------------
extern "C" void kernel_launch(void* const* d_in, const int* in_sizes, int n_in,
                              void* d_out, int out_size)
{
    const float* x      = (const float*)d_in[0];
    const float* w_qkv  = (const float*)d_in[1];
    const float* b_qkv  = (const float*)d_in[2];
    const float* rel    = (const float*)d_in[3];
    const float* w_proj = (const float*)d_in[4];
    const float* b_proj = (const float*)d_in[5];
    float* out = (float*)d_out;
    (void)in_sizes; (void)n_in; (void)out_size;

    float *qkv, *att, *xc, *wqkvc, *wprojc;
    cudaGetSymbolAddress((void**)&qkv,    g_qkv);
    cudaGetSymbolAddress((void**)&att,    g_att);
    cudaGetSymbolAddress((void**)&xc,     g_xc);
    cudaGetSymbolAddress((void**)&wqkvc,  g_wqkv_c);
    cudaGetSymbolAddress((void**)&wprojc, g_wproj_c);

    cudaFuncSetAttribute(gemm_tf32, cudaFuncAttributeMaxDynamicSharedMemorySize, SMEM_BYTES);

    // 0) TF32 pre-round
    cvt_tf32_pass<<<4096, 256>>>((const float4*)x,      (float4*)xc,     (M_ROWS * DIM) / 4);
    cvt_tf32_pass<<<192, 256>>>((const float4*)w_qkv,  (float4*)wqkvc,  (DIM * QKV_DIM) / 4);
    cvt_tf32_pass<<<64,  256>>>((const float4*)w_proj, (float4*)wprojc, (DIM * DIM) / 4);

    // 1) QKV GEMM: [131072,512] @ [512,1536] + b_qkv
    {
        dim3 grid(QKV_DIM / GBN, M_ROWS / GBM);
        gemm_tf32<<<grid, 256, SMEM_BYTES>>>(xc, wqkvc, b_qkv, qkv, M_ROWS, QKV_DIM, DIM);
    }

    // 2) Windowed attention (writes g_att tf32-rounded)
    {
        dim3 grid(B_WIN, HEADS);
        attn_kernel<<<grid, 64>>>(rel);
    }

    // 3) Output projection: [131072,512] @ [512,512] + b_proj
    {
        dim3 grid(DIM / GBN, M_ROWS / GBM);
        gemm_tf32<<<grid, 256, SMEM_BYTES>>>(att, wprojc, b_proj, out, M_ROWS, DIM, DIM);
    }
}